// round 8
// baseline (speedup 1.0000x reference)
#include <cuda_runtime.h>
#include <cstdint>

// Scratch for per-(batch,channel) generated 3x3 kernels: 16*64*9 floats.
__device__ float g_kern[16 * 576];

// ------------------------------ helpers ------------------------------------
__device__ __forceinline__ uint32_t f32_tf32(float f) {
    uint32_t u;
    asm("cvt.rna.tf32.f32 %0, %1;" : "=r"(u) : "f"(f));
    return u;
}
__device__ __forceinline__ uint32_t smem_u32(const void* p) {
    uint32_t a;
    asm("{ .reg .u64 t; cvta.to.shared.u64 t, %1; cvt.u32.u64 %0, t; }"
        : "=r"(a) : "l"(p));
    return a;
}
__device__ __forceinline__ void cp_async16(uint32_t saddr, const void* gaddr,
                                           uint32_t src_sz) {
    asm volatile("cp.async.cg.shared.global [%0], [%1], 16, %2;"
                 :: "r"(saddr), "l"(gaddr), "r"(src_sz) : "memory");
}
#define CP_COMMIT() asm volatile("cp.async.commit_group;" ::: "memory")
#define CP_WAIT(n)  asm volatile("cp.async.wait_group %0;" :: "n"(n) : "memory")

// D += A*B, m16n8k8 tf32 (tensor pipe, fp32 accumulate in registers)
__device__ __forceinline__ void mma_tf32(float* d, const uint32_t* a,
                                         const uint32_t* b) {
    asm volatile(
        "mma.sync.aligned.m16n8k8.row.col.f32.tf32.tf32.f32 "
        "{%0,%1,%2,%3}, {%4,%5,%6,%7}, {%8,%9}, {%0,%1,%2,%3};"
        : "+f"(d[0]), "+f"(d[1]), "+f"(d[2]), "+f"(d[3])
        : "r"(a[0]), "r"(a[1]), "r"(a[2]), "r"(a[3]), "r"(b[0]), "r"(b[1]));
}

// ---------------------------------------------------------------------------
// Kernel A: kernel-generating MLP. Grid 16 x 576 threads; one output/thread.
// ---------------------------------------------------------------------------
__global__ void gen_kern_kernel(const float* __restrict__ d,
                                const float* __restrict__ Wk1,
                                const float* __restrict__ Wk2) {
    const int b = blockIdx.x;
    const int t = threadIdx.x;  // 0..575
    __shared__ float ds[64];
    __shared__ float hid[64];

    if (t < 64) ds[t] = d[b * 64 + t];
    __syncthreads();
    if (t < 64) {
        float s = 0.f;
#pragma unroll 16
        for (int i = 0; i < 64; i++) s += ds[i] * Wk1[t * 64 + i];
        hid[t] = (s >= 0.f) ? s : 0.1f * s;
    }
    __syncthreads();

    float a = 0.f;
    const float* wp = Wk2 + (size_t)t * 64;
#pragma unroll 16
    for (int j = 0; j < 64; j++) a += hid[j] * wp[j];
    g_kern[b * 576 + t] = a;
}

// ---------------------------------------------------------------------------
// Kernel B: fused dynamic depthwise 3x3 + LeakyReLU -> tf32 mma.sync GEMM
// (pointwise 1x1) + bias; cp.async channel pipeline.
//
// Grid (4,16,16): block = 32x8 pixel tile of one batch, 256 threads (8 warps).
// GEMM: M=256 pixels, N=64 outputs, K=64 channels, 4 chunks of 16.
//
// Phase-1 mapping: thread t -> ch=t>>4, row=(t>>1)&7, sh=t&1; computes 16 px
// (one row, cols 16sh..16sh+15) of one channel: 18 LDS.128 / 16 outputs,
// conflict-free (quarter-warp banks 12r+16s all distinct).
//
// vs layout: vs[k][pixel] with KS=296 floats per k and pixel mapped as
// addr = k*296 + (px>>5)*36 + (px&31). Writer STS.128 banks 4r+16s distinct;
// GEMM af reads banks 8*tig+g distinct (296 mod 32 == 8).
//
// Smem (bytes):
//   xs[2] @0     : halo chunk, 16ch x 10r x 44f (stride 176B), 2 bufs (56320)
//                  (reused as 32x264 epilogue stage after GEMM)
//   vs    @56320 : V tf32, 16 x 296 floats                         (18944)
//   wct   @75264 : Wc tf32, [k=c][n=o] stride 72                   (18432)
//   kk    @93696 : 64 x 12 f32                                     ( 3072)
//   bcs   @96768 : bias f32[64]                                    (  256)
// total 97024 -> 2 blocks/SM.
// ---------------------------------------------------------------------------
#define KC          16
#define XS_OFF      0
#define XS_BUF      28160            // 16*440*4
#define VS_OFF      56320
#define WCT_OFF     75264
#define KK_OFF      93696
#define BC_OFF      96768
#define SMEM_TOTAL  97024
#define KS          296
#define WCT_STRIDE  72
#define STG_STRIDE  264

__global__ __launch_bounds__(256, 2)
void da_conv_mma(const float* __restrict__ x,
                 const float* __restrict__ Wc,
                 const float* __restrict__ bc,
                 float* __restrict__ out) {
    extern __shared__ char smem[];
    const uint32_t smb = smem_u32(smem);
    uint32_t* wct = (uint32_t*)(smem + WCT_OFF);
    float*    kk  = (float*)(smem + KK_OFF);
    float*    bcs = (float*)(smem + BC_OFF);
    uint32_t* vs  = (uint32_t*)(smem + VS_OFF);
    float*    stage = (float*)(smem + XS_OFF);   // epilogue reuse

    const int t  = threadIdx.x;
    const int b  = blockIdx.z, bx = blockIdx.x, by = blockIdx.y;
    const int w  = t >> 5, lane = t & 31;

    // ---- static tiles: Wc -> wct (tf32), kernels, bias --------------------
    for (int i = t; i < 4096; i += 256) {
        int o = i >> 6, c = i & 63;
        wct[c * WCT_STRIDE + o] = f32_tf32(Wc[i]);
    }
    for (int i = t; i < 576; i += 256) {
        int c = i / 9, j = i - c * 9;
        kk[c * 12 + j] = g_kern[b * 576 + i];
    }
    if (t < 64) bcs[t] = bc[t];

    // ---- halo loader: 16B cp.async, slab mapping (threads 0..159) ---------
    const int h0  = by * 8 - 1;
    const int w0p = bx * 32;
    const float* xb = x + (size_t)b * 64 * 16384;

    const int  lcl = t & 15;            // channel-in-chunk this thread loads
    const int  lk  = t >> 4;            // 16B chunk index 0..9 (t<160)
    const int  cb  = w0p - 4 + lk * 4;  // global col of chunk start
    const bool vc  = (unsigned)cb <= 124u;
    const bool lactive = t < 160;
    const float* lsrc0 = xb + (size_t)lcl * 16384 + (vc ? cb : 0);
    const uint32_t ldst0 = smb + XS_OFF + (uint32_t)(lcl * 1760 + lk * 16);

    auto load_chunk = [&](int c, int buf) {
        if (lactive) {
            const float* s0 = lsrc0 + (size_t)c * KC * 16384;
            uint32_t d0 = ldst0 + (uint32_t)buf * XS_BUF;
#pragma unroll
            for (int r = 0; r < 10; r++) {
                int gh = h0 + r;
                bool v = vc && ((unsigned)gh < 128u);
                cp_async16(d0 + r * 176, s0 + (v ? gh * 128 : 0), v ? 16u : 0u);
            }
        }
        CP_COMMIT();
    };

    load_chunk(0, 0);
    load_chunk(1, 1);

    // ---- GEMM thread mapping (fragment layout verified R5-R7) -------------
    const int wm = w >> 1, wn = w & 1;
    const int g = lane >> 2, tig = lane & 3;
    const int m_base = wm * 64;
    const int n_base = wn * 32;

    // per-mt vs offsets: R = wm*2 + (mt>>1), C = (mt&1)*16 + g
    int rowoff[4];
#pragma unroll
    for (int mt = 0; mt < 4; mt++)
        rowoff[mt] = (wm * 2 + (mt >> 1)) * 36 + (mt & 1) * 16 + g;

    float acc[4][4][4];
#pragma unroll
    for (int mt = 0; mt < 4; mt++)
#pragma unroll
        for (int nt = 0; nt < 4; nt++)
#pragma unroll
            for (int r = 0; r < 4; r++) acc[mt][nt][r] = 0.f;

    // ---- phase-1 mapping: 16 px x 1 row x 1 ch per thread -----------------
    const int ch_l = t >> 4;            // channel in chunk 0..15
    const int prw  = (t >> 1) & 7;      // output row 0..7
    const int psh  = t & 1;             // col half 0..1

#pragma unroll
    for (int c = 0; c < 4; c++) {
        const int buf = c & 1;
        if (c < 3) { CP_WAIT(1); } else { CP_WAIT(0); }
        __syncthreads();

        // ---- phase 1: dwconv 3x3 + lrelu, 16px x 1ch per thread -----------
        {
            const float* xs = (const float*)(smem + XS_OFF + buf * XS_BUF);
            const float* kcp = kk + (c * KC + ch_l) * 12;
            const float* xbase = xs + ch_l * 440 + prw * 44 + 16 * psh;

            float a16[16];
#pragma unroll
            for (int p = 0; p < 16; p++) a16[p] = 0.f;

#pragma unroll
            for (int r = 0; r < 3; r++) {
                float k0 = kcp[r * 3 + 0];
                float k1 = kcp[r * 3 + 1];
                float k2 = kcp[r * 3 + 2];
                const float4* xr = (const float4*)(xbase + r * 44);
                float4 f0 = xr[0], f1 = xr[1], f2 = xr[2];
                float4 f3 = xr[3], f4 = xr[4], f5 = xr[5];
                float v[24] = {f0.x, f0.y, f0.z, f0.w, f1.x, f1.y, f1.z, f1.w,
                               f2.x, f2.y, f2.z, f2.w, f3.x, f3.y, f3.z, f3.w,
                               f4.x, f4.y, f4.z, f4.w, f5.x, f5.y, f5.z, f5.w};
#pragma unroll
                for (int p = 0; p < 16; p++)
                    a16[p] += v[p + 3] * k0 + v[p + 4] * k1 + v[p + 5] * k2;
            }

            uint32_t* vrow = vs + ch_l * KS + prw * 36 + 16 * psh;
#pragma unroll
            for (int q = 0; q < 4; q++) {
                float v0 = fmaxf(a16[4 * q + 0], 0.1f * a16[4 * q + 0]);
                float v1 = fmaxf(a16[4 * q + 1], 0.1f * a16[4 * q + 1]);
                float v2 = fmaxf(a16[4 * q + 2], 0.1f * a16[4 * q + 2]);
                float v3 = fmaxf(a16[4 * q + 3], 0.1f * a16[4 * q + 3]);
                *(uint4*)(vrow + 4 * q) = make_uint4(
                    f32_tf32(v0), f32_tf32(v1), f32_tf32(v2), f32_tf32(v3));
            }
        }
        __syncthreads();

        // prefetch chunk c+2 into the buffer we just drained
        if (c < 2) load_chunk(c + 2, buf);

        // ---- phase 2: 2 k-steps of the tf32 tensor GEMM -------------------
#pragma unroll
        for (int s2 = 0; s2 < 2; s2++) {
            const int k0 = s2 * 8;
            uint32_t bf[4][2];
#pragma unroll
            for (int nt = 0; nt < 4; nt++) {
                int n = n_base + nt * 8 + g;
                bf[nt][0] = wct[(c * KC + k0 + tig) * WCT_STRIDE + n];
                bf[nt][1] = wct[(c * KC + k0 + tig + 4) * WCT_STRIDE + n];
            }
            uint32_t af[4][4];
#pragma unroll
            for (int mt = 0; mt < 4; mt++) {
                af[mt][0] = vs[(k0 + tig) * KS + rowoff[mt]];
                af[mt][1] = vs[(k0 + tig) * KS + rowoff[mt] + 8];
                af[mt][2] = vs[(k0 + tig + 4) * KS + rowoff[mt]];
                af[mt][3] = vs[(k0 + tig + 4) * KS + rowoff[mt] + 8];
            }
#pragma unroll
            for (int mt = 0; mt < 4; mt++)
#pragma unroll
                for (int nt = 0; nt < 4; nt++)
                    mma_tf32(acc[mt][nt], af[mt], bf[nt]);
        }
    }

    // ---- epilogue: stage through smem (xs region, now free) -> STG --------
    float* obase = out + (size_t)b * 64 * 16384 + (size_t)(by * 8) * 128 + bx * 32;
    __syncthreads();
#pragma unroll
    for (int nc = 0; nc < 2; nc++) {
        if (wn == nc) {
#pragma unroll
            for (int mt = 0; mt < 4; mt++)
#pragma unroll
                for (int nt = 0; nt < 4; nt++) {
                    int ol = nt * 8 + 2 * tig;
                    int p0 = m_base + mt * 16 + g;
                    stage[ol * STG_STRIDE + p0]            = acc[mt][nt][0];
                    stage[(ol + 1) * STG_STRIDE + p0]      = acc[mt][nt][1];
                    stage[ol * STG_STRIDE + p0 + 8]        = acc[mt][nt][2];
                    stage[(ol + 1) * STG_STRIDE + p0 + 8]  = acc[mt][nt][3];
                }
        }
        __syncthreads();
#pragma unroll 8
        for (int j = 0; j < 32; j++) {
            int idx = t + 256 * j;
            int ol = idx >> 8, pix = idx & 255;
            float v = stage[ol * STG_STRIDE + pix] + bcs[nc * 32 + ol];
            obase[(size_t)(nc * 32 + ol) * 16384 + (pix >> 5) * 128 + (pix & 31)] = v;
        }
        __syncthreads();
    }
}

// ---------------------------------------------------------------------------
// Launch: inputs x, d, Wk1, Wk2, Wc, bc. Output float32 (16,64,128,128).
// ---------------------------------------------------------------------------
extern "C" void kernel_launch(void* const* d_in, const int* in_sizes, int n_in,
                              void* d_out, int out_size) {
    const float* x   = (const float*)d_in[0];
    const float* d   = (const float*)d_in[1];
    const float* Wk1 = (const float*)d_in[2];
    const float* Wk2 = (const float*)d_in[3];
    const float* Wc  = (const float*)d_in[4];
    const float* bc  = (const float*)d_in[5];
    float* out = (float*)d_out;

    gen_kern_kernel<<<16, 576>>>(d, Wk1, Wk2);

    cudaFuncSetAttribute(da_conv_mma,
                         cudaFuncAttributeMaxDynamicSharedMemorySize,
                         SMEM_TOTAL);
    dim3 grid(4, 16, 16);
    da_conv_mma<<<grid, 256, SMEM_TOTAL>>>(x, Wc, bc, out);
}

// round 9
// speedup vs baseline: 1.2594x; 1.2594x over previous
#include <cuda_runtime.h>
#include <cstdint>

// Scratch for per-(batch,channel) generated 3x3 kernels: 16*64*9 floats.
__device__ float g_kern[16 * 576];

// ------------------------------ helpers ------------------------------------
__device__ __forceinline__ uint32_t f32_tf32(float f) {
    uint32_t u;
    asm("cvt.rna.tf32.f32 %0, %1;" : "=r"(u) : "f"(f));
    return u;
}
__device__ __forceinline__ uint32_t smem_u32(const void* p) {
    uint32_t a;
    asm("{ .reg .u64 t; cvta.to.shared.u64 t, %1; cvt.u32.u64 %0, t; }"
        : "=r"(a) : "l"(p));
    return a;
}
__device__ __forceinline__ void cp_async16(uint32_t saddr, const void* gaddr,
                                           uint32_t src_sz) {
    asm volatile("cp.async.cg.shared.global [%0], [%1], 16, %2;"
                 :: "r"(saddr), "l"(gaddr), "r"(src_sz) : "memory");
}
#define CP_COMMIT() asm volatile("cp.async.commit_group;" ::: "memory")
#define CP_WAIT(n)  asm volatile("cp.async.wait_group %0;" :: "n"(n) : "memory")

// D += A*B, m16n8k8 tf32 (tensor pipe, fp32 accumulate in registers)
__device__ __forceinline__ void mma_tf32(float* d, const uint32_t* a,
                                         const uint32_t* b) {
    asm volatile(
        "mma.sync.aligned.m16n8k8.row.col.f32.tf32.tf32.f32 "
        "{%0,%1,%2,%3}, {%4,%5,%6,%7}, {%8,%9}, {%0,%1,%2,%3};"
        : "+f"(d[0]), "+f"(d[1]), "+f"(d[2]), "+f"(d[3])
        : "r"(a[0]), "r"(a[1]), "r"(a[2]), "r"(a[3]), "r"(b[0]), "r"(b[1]));
}

// ---------------------------------------------------------------------------
// Kernel A: kernel-generating MLP.
// Grid (16,9) x 256 threads (144 blocks ~ one wave).
// Block (b, mb): outputs m = mb*64 .. mb*64+63 of batch b.
// Layer 1: 64 threads compute hid (tiny). Layer 2: warp-per-output,
// coalesced Wk2 loads + shfl butterfly reduction; 8 outputs per warp.
// ---------------------------------------------------------------------------
__global__ void gen_kern_kernel(const float* __restrict__ d,
                                const float* __restrict__ Wk1,
                                const float* __restrict__ Wk2) {
    const int b = blockIdx.x;
    const int t = threadIdx.x;  // 0..255
    const int w = t >> 5, lane = t & 31;
    __shared__ float ds[64];
    __shared__ float hid[64];

    if (t < 64) ds[t] = d[b * 64 + t];
    __syncthreads();
    if (t < 64) {
        float s = 0.f;
#pragma unroll 16
        for (int i = 0; i < 64; i++) s += ds[i] * Wk1[t * 64 + i];
        hid[t] = (s >= 0.f) ? s : 0.1f * s;
    }
    __syncthreads();

    const float h0 = hid[lane];
    const float h1 = hid[lane + 32];
#pragma unroll
    for (int q = 0; q < 8; q++) {
        const int m = blockIdx.y * 64 + w * 8 + q;
        const float* wp = Wk2 + (size_t)m * 64;
        float p = h0 * wp[lane] + h1 * wp[lane + 32];
#pragma unroll
        for (int sh = 16; sh > 0; sh >>= 1)
            p += __shfl_xor_sync(0xFFFFFFFFu, p, sh);
        if (lane == 0) g_kern[b * 576 + m] = p;
    }
}

// ---------------------------------------------------------------------------
// Kernel B: fused dynamic depthwise 3x3 + LeakyReLU -> tf32 mma.sync GEMM
// (pointwise 1x1) + bias; cp.async channel pipeline.  (R8-verified, unchanged)
//
// Grid (4,16,16): block = 32x8 pixel tile of one batch, 256 threads (8 warps).
// GEMM: M=256 pixels, N=64 outputs, K=64 channels, 4 chunks of 16.
//
// Phase-1 mapping: thread t -> ch=t>>4, row=(t>>1)&7, sh=t&1; computes 16 px
// (one row, cols 16sh..16sh+15) of one channel: 18 LDS.128 / 16 outputs,
// conflict-free (quarter-warp banks 12r+16s all distinct).
//
// vs layout: vs[k][pixel] with KS=296 floats per k and pixel mapped as
// addr = k*296 + (px>>5)*36 + (px&31). Writer STS.128 banks 4r+16s distinct;
// GEMM af reads banks 8*tig+g distinct (296 mod 32 == 8).
//
// Smem (bytes):
//   xs[2] @0     : halo chunk, 16ch x 10r x 44f (stride 176B), 2 bufs (56320)
//                  (reused as 32x264 epilogue stage after GEMM)
//   vs    @56320 : V tf32, 16 x 296 floats                         (18944)
//   wct   @75264 : Wc tf32, [k=c][n=o] stride 72                   (18432)
//   kk    @93696 : 64 x 12 f32                                     ( 3072)
//   bcs   @96768 : bias f32[64]                                    (  256)
// total 97024 -> 2 blocks/SM.
// ---------------------------------------------------------------------------
#define KC          16
#define XS_OFF      0
#define XS_BUF      28160            // 16*440*4
#define VS_OFF      56320
#define WCT_OFF     75264
#define KK_OFF      93696
#define BC_OFF      96768
#define SMEM_TOTAL  97024
#define KS          296
#define WCT_STRIDE  72
#define STG_STRIDE  264

__global__ __launch_bounds__(256, 2)
void da_conv_mma(const float* __restrict__ x,
                 const float* __restrict__ Wc,
                 const float* __restrict__ bc,
                 float* __restrict__ out) {
    extern __shared__ char smem[];
    const uint32_t smb = smem_u32(smem);
    uint32_t* wct = (uint32_t*)(smem + WCT_OFF);
    float*    kk  = (float*)(smem + KK_OFF);
    float*    bcs = (float*)(smem + BC_OFF);
    uint32_t* vs  = (uint32_t*)(smem + VS_OFF);
    float*    stage = (float*)(smem + XS_OFF);   // epilogue reuse

    const int t  = threadIdx.x;
    const int b  = blockIdx.z, bx = blockIdx.x, by = blockIdx.y;
    const int w  = t >> 5, lane = t & 31;

    // ---- static tiles: Wc -> wct (tf32), kernels, bias --------------------
    for (int i = t; i < 4096; i += 256) {
        int o = i >> 6, c = i & 63;
        wct[c * WCT_STRIDE + o] = f32_tf32(Wc[i]);
    }
    for (int i = t; i < 576; i += 256) {
        int c = i / 9, j = i - c * 9;
        kk[c * 12 + j] = g_kern[b * 576 + i];
    }
    if (t < 64) bcs[t] = bc[t];

    // ---- halo loader: 16B cp.async, slab mapping (threads 0..159) ---------
    const int h0  = by * 8 - 1;
    const int w0p = bx * 32;
    const float* xb = x + (size_t)b * 64 * 16384;

    const int  lcl = t & 15;            // channel-in-chunk this thread loads
    const int  lk  = t >> 4;            // 16B chunk index 0..9 (t<160)
    const int  cb  = w0p - 4 + lk * 4;  // global col of chunk start
    const bool vc  = (unsigned)cb <= 124u;
    const bool lactive = t < 160;
    const float* lsrc0 = xb + (size_t)lcl * 16384 + (vc ? cb : 0);
    const uint32_t ldst0 = smb + XS_OFF + (uint32_t)(lcl * 1760 + lk * 16);

    auto load_chunk = [&](int c, int buf) {
        if (lactive) {
            const float* s0 = lsrc0 + (size_t)c * KC * 16384;
            uint32_t d0 = ldst0 + (uint32_t)buf * XS_BUF;
#pragma unroll
            for (int r = 0; r < 10; r++) {
                int gh = h0 + r;
                bool v = vc && ((unsigned)gh < 128u);
                cp_async16(d0 + r * 176, s0 + (v ? gh * 128 : 0), v ? 16u : 0u);
            }
        }
        CP_COMMIT();
    };

    load_chunk(0, 0);
    load_chunk(1, 1);

    // ---- GEMM thread mapping (fragment layout verified R5-R8) -------------
    const int wm = w >> 1, wn = w & 1;
    const int g = lane >> 2, tig = lane & 3;
    const int m_base = wm * 64;
    const int n_base = wn * 32;

    // per-mt vs offsets: R = wm*2 + (mt>>1), C = (mt&1)*16 + g
    int rowoff[4];
#pragma unroll
    for (int mt = 0; mt < 4; mt++)
        rowoff[mt] = (wm * 2 + (mt >> 1)) * 36 + (mt & 1) * 16 + g;

    float acc[4][4][4];
#pragma unroll
    for (int mt = 0; mt < 4; mt++)
#pragma unroll
        for (int nt = 0; nt < 4; nt++)
#pragma unroll
            for (int r = 0; r < 4; r++) acc[mt][nt][r] = 0.f;

    // ---- phase-1 mapping: 16 px x 1 row x 1 ch per thread -----------------
    const int ch_l = t >> 4;            // channel in chunk 0..15
    const int prw  = (t >> 1) & 7;      // output row 0..7
    const int psh  = t & 1;             // col half 0..1

#pragma unroll
    for (int c = 0; c < 4; c++) {
        const int buf = c & 1;
        if (c < 3) { CP_WAIT(1); } else { CP_WAIT(0); }
        __syncthreads();

        // ---- phase 1: dwconv 3x3 + lrelu, 16px x 1ch per thread -----------
        {
            const float* xs = (const float*)(smem + XS_OFF + buf * XS_BUF);
            const float* kcp = kk + (c * KC + ch_l) * 12;
            const float* xbase = xs + ch_l * 440 + prw * 44 + 16 * psh;

            float a16[16];
#pragma unroll
            for (int p = 0; p < 16; p++) a16[p] = 0.f;

#pragma unroll
            for (int r = 0; r < 3; r++) {
                float k0 = kcp[r * 3 + 0];
                float k1 = kcp[r * 3 + 1];
                float k2 = kcp[r * 3 + 2];
                const float4* xr = (const float4*)(xbase + r * 44);
                float4 f0 = xr[0], f1 = xr[1], f2 = xr[2];
                float4 f3 = xr[3], f4 = xr[4], f5 = xr[5];
                float v[24] = {f0.x, f0.y, f0.z, f0.w, f1.x, f1.y, f1.z, f1.w,
                               f2.x, f2.y, f2.z, f2.w, f3.x, f3.y, f3.z, f3.w,
                               f4.x, f4.y, f4.z, f4.w, f5.x, f5.y, f5.z, f5.w};
#pragma unroll
                for (int p = 0; p < 16; p++)
                    a16[p] += v[p + 3] * k0 + v[p + 4] * k1 + v[p + 5] * k2;
            }

            uint32_t* vrow = vs + ch_l * KS + prw * 36 + 16 * psh;
#pragma unroll
            for (int q = 0; q < 4; q++) {
                float v0 = fmaxf(a16[4 * q + 0], 0.1f * a16[4 * q + 0]);
                float v1 = fmaxf(a16[4 * q + 1], 0.1f * a16[4 * q + 1]);
                float v2 = fmaxf(a16[4 * q + 2], 0.1f * a16[4 * q + 2]);
                float v3 = fmaxf(a16[4 * q + 3], 0.1f * a16[4 * q + 3]);
                *(uint4*)(vrow + 4 * q) = make_uint4(
                    f32_tf32(v0), f32_tf32(v1), f32_tf32(v2), f32_tf32(v3));
            }
        }
        __syncthreads();

        // prefetch chunk c+2 into the buffer we just drained
        if (c < 2) load_chunk(c + 2, buf);

        // ---- phase 2: 2 k-steps of the tf32 tensor GEMM -------------------
#pragma unroll
        for (int s2 = 0; s2 < 2; s2++) {
            const int k0 = s2 * 8;
            uint32_t bf[4][2];
#pragma unroll
            for (int nt = 0; nt < 4; nt++) {
                int n = n_base + nt * 8 + g;
                bf[nt][0] = wct[(c * KC + k0 + tig) * WCT_STRIDE + n];
                bf[nt][1] = wct[(c * KC + k0 + tig + 4) * WCT_STRIDE + n];
            }
            uint32_t af[4][4];
#pragma unroll
            for (int mt = 0; mt < 4; mt++) {
                af[mt][0] = vs[(k0 + tig) * KS + rowoff[mt]];
                af[mt][1] = vs[(k0 + tig) * KS + rowoff[mt] + 8];
                af[mt][2] = vs[(k0 + tig + 4) * KS + rowoff[mt]];
                af[mt][3] = vs[(k0 + tig + 4) * KS + rowoff[mt] + 8];
            }
#pragma unroll
            for (int mt = 0; mt < 4; mt++)
#pragma unroll
                for (int nt = 0; nt < 4; nt++)
                    mma_tf32(acc[mt][nt], af[mt], bf[nt]);
        }
    }

    // ---- epilogue: stage through smem (xs region, now free) -> STG --------
    float* obase = out + (size_t)b * 64 * 16384 + (size_t)(by * 8) * 128 + bx * 32;
    __syncthreads();
#pragma unroll
    for (int nc = 0; nc < 2; nc++) {
        if (wn == nc) {
#pragma unroll
            for (int mt = 0; mt < 4; mt++)
#pragma unroll
                for (int nt = 0; nt < 4; nt++) {
                    int ol = nt * 8 + 2 * tig;
                    int p0 = m_base + mt * 16 + g;
                    stage[ol * STG_STRIDE + p0]            = acc[mt][nt][0];
                    stage[(ol + 1) * STG_STRIDE + p0]      = acc[mt][nt][1];
                    stage[ol * STG_STRIDE + p0 + 8]        = acc[mt][nt][2];
                    stage[(ol + 1) * STG_STRIDE + p0 + 8]  = acc[mt][nt][3];
                }
        }
        __syncthreads();
#pragma unroll 8
        for (int j = 0; j < 32; j++) {
            int idx = t + 256 * j;
            int ol = idx >> 8, pix = idx & 255;
            float v = stage[ol * STG_STRIDE + pix] + bcs[nc * 32 + ol];
            obase[(size_t)(nc * 32 + ol) * 16384 + (pix >> 5) * 128 + (pix & 31)] = v;
        }
        __syncthreads();
    }
}

// ---------------------------------------------------------------------------
// Launch: inputs x, d, Wk1, Wk2, Wc, bc. Output float32 (16,64,128,128).
// ---------------------------------------------------------------------------
extern "C" void kernel_launch(void* const* d_in, const int* in_sizes, int n_in,
                              void* d_out, int out_size) {
    const float* x   = (const float*)d_in[0];
    const float* d   = (const float*)d_in[1];
    const float* Wk1 = (const float*)d_in[2];
    const float* Wk2 = (const float*)d_in[3];
    const float* Wc  = (const float*)d_in[4];
    const float* bc  = (const float*)d_in[5];
    float* out = (float*)d_out;

    gen_kern_kernel<<<dim3(16, 9), 256>>>(d, Wk1, Wk2);

    cudaFuncSetAttribute(da_conv_mma,
                         cudaFuncAttributeMaxDynamicSharedMemorySize,
                         SMEM_TOTAL);
    dim3 grid(4, 16, 16);
    da_conv_mma<<<grid, 256, SMEM_TOTAL>>>(x, Wc, bc, out);
}